// round 5
// baseline (speedup 1.0000x reference)
#include <cuda_runtime.h>
#include <math.h>

#define NBOX 1024
#define EPSF 1e-8f
#define NMS_TH 0.1f
#define MAXP (1<<18)
#define MAXSP (1<<16)
#define GRID 148
#define TPB 512
#define NTH (GRID*TPB)
#define FULLM 0xFFFFFFFFu

struct Box {
    float cx, cy, hx, hy, cs, sn;
    float corx[4], cory[4];
    float rad, zmin, zmax, area, vol;
    float pad;
};

__device__ Box g_gt[NBOX];
__device__ Box g_pred[NBOX];
__device__ float4 g_qgt[NBOX];     // cx, cy, rad, zmin
__device__ float4 g_qpred[NBOX];
__device__ float g_zmaxgt[NBOX];
__device__ float g_zmaxpred[NBOX];
__device__ unsigned g_supp[NBOX * 32];   // sorted-space suppression bits (upper-tri)
__device__ int g_order[NBOX];
__device__ int g_pos[NBOX];
__device__ int g_keep_orig[NBOX];
__device__ int g_cnt_gg;
__device__ int g_cnt_pg;
__device__ int g_cnt_sp;
__device__ unsigned g_pairs_gg[MAXP];
__device__ unsigned g_pairs_pg[MAXP];
__device__ unsigned g_sp[MAXSP];         // orig-space suppression pairs
__device__ float g_ioupg[MAXP];
__device__ unsigned long long g_rowbest[NBOX];

// monotonic grid barrier (replay-safe)
__device__ unsigned g_bar_arrive;
__device__ volatile unsigned g_bar_release;
// sub-barrier for blocks 1..GRID-1
__device__ unsigned g_sub_arrive;
__device__ volatile unsigned g_sub_release;

__device__ __forceinline__ void gbar() {
    __syncthreads();
    if (threadIdx.x == 0) {
        __threadfence();
        unsigned t = atomicAdd(&g_bar_arrive, 1u) + 1u;
        unsigned need = ((t + GRID - 1u) / GRID) * GRID;
        if (t == need) g_bar_release = need;
        else while (g_bar_release < need) { __nanosleep(32); }
        __threadfence();
    }
    __syncthreads();
}

__device__ __forceinline__ void subbar() {   // blocks 1..GRID-1 only
    __syncthreads();
    if (threadIdx.x == 0) {
        __threadfence();
        unsigned t = atomicAdd(&g_sub_arrive, 1u) + 1u;
        unsigned nb = GRID - 1u;
        unsigned need = ((t + nb - 1u) / nb) * nb;
        if (t == need) g_sub_release = need;
        else while (g_sub_release < need) { __nanosleep(32); }
        __threadfence();
    }
    __syncthreads();
}

// ---------------------------------------------------------------------------
// Rotated-rect intersection — bit-identical to the passing R1 math.
// ---------------------------------------------------------------------------
__device__ float inter_area(const Box& a, const Box& b) {
    float px[24], py[24];
    int k = 0;

#pragma unroll
    for (int q = 0; q < 4; q++) {
        float dxp = a.corx[q] - b.cx, dyp = a.cory[q] - b.cy;
        float lx =  dxp * b.cs + dyp * b.sn;
        float ly = -dxp * b.sn + dyp * b.cs;
        if (fabsf(lx) <= b.hx + 1e-5f && fabsf(ly) <= b.hy + 1e-5f) {
            px[k] = a.corx[q]; py[k] = a.cory[q]; k++;
        }
    }
#pragma unroll
    for (int q = 0; q < 4; q++) {
        float dxp = b.corx[q] - a.cx, dyp = b.cory[q] - a.cy;
        float lx =  dxp * a.cs + dyp * a.sn;
        float ly = -dxp * a.sn + dyp * a.cs;
        if (fabsf(lx) <= a.hx + 1e-5f && fabsf(ly) <= a.hy + 1e-5f) {
            px[k] = b.corx[q]; py[k] = b.cory[q]; k++;
        }
    }
#pragma unroll
    for (int p = 0; p < 4; p++) {
        float a0x = a.corx[p], a0y = a.cory[p];
        float a1x = a.corx[(p + 1) & 3], a1y = a.cory[(p + 1) & 3];
        float d1x = a1x - a0x, d1y = a1y - a0y;
#pragma unroll
        for (int q = 0; q < 4; q++) {
            float b0x = b.corx[q], b0y = b.cory[q];
            float b1x = b.corx[(q + 1) & 3], b1y = b.cory[(q + 1) & 3];
            float d2x = b1x - b0x, d2y = b1y - b0y;
            float r0x = b0x - a0x, r0y = b0y - a0y;
            float den = d1x * d2y - d1y * d2x;
            if (fabsf(den) > EPSF) {
                float t = (r0x * d2y - r0y * d2x) / den;
                float u = (r0x * d1y - r0y * d1x) / den;
                if (t >= 0.f && t <= 1.f && u >= 0.f && u <= 1.f) {
                    px[k] = a0x + t * d1x;
                    py[k] = a0y + t * d1y;
                    k++;
                }
            }
        }
    }

    if (k < 3) return 0.f;

    float sx = 0.f, sy = 0.f;
    for (int i = 0; i < k; i++) { sx += px[i]; sy += py[i]; }
    float fk = (float)k;
    float cxm = sx / fk, cym = sy / fk;

    float ang[24];
    for (int i = 0; i < k; i++) {
        px[i] -= cxm; py[i] -= cym;
        ang[i] = atan2f(py[i], px[i]);
    }
    for (int i = 1; i < k; i++) {
        float ax = px[i], ay = py[i], aa = ang[i];
        int j = i - 1;
        while (j >= 0 && ang[j] > aa) {
            px[j + 1] = px[j]; py[j + 1] = py[j]; ang[j + 1] = ang[j];
            j--;
        }
        px[j + 1] = ax; py[j + 1] = ay; ang[j + 1] = aa;
    }
    float s = 0.f;
    for (int i = 0; i < k; i++) {
        int j = (i + 1 == k) ? 0 : (i + 1);
        s += px[i] * py[j] - py[i] * px[j];
    }
    return 0.5f * fabsf(s);
}

__device__ __forceinline__ void emit_pair(bool pass, unsigned code,
                                          int* cnt, unsigned* arr) {
    unsigned m = __ballot_sync(FULLM, pass);
    if (!m) return;
    int lane = threadIdx.x & 31;
    int leader = __ffs(m) - 1;
    int base = 0;
    if (lane == leader) base = atomicAdd(cnt, __popc(m));
    base = __shfl_sync(FULLM, base, leader);
    if (pass) {
        int idx = base + __popc(m & ((1u << lane) - 1u));
        if (idx < MAXP) arr[idx] = code;
    }
}

// ---------------------------------------------------------------------------
__global__ __launch_bounds__(TPB, 1)
void mega_kernel(const float* __restrict__ labels,
                 const float* __restrict__ pred_boxes,
                 const float* __restrict__ gt_boxes,
                 const float* __restrict__ cls,
                 float* __restrict__ out) {
    extern __shared__ unsigned s_mem[];   // 128KB: sort keys (B) / supp copy (C)
    const int tid = threadIdx.x;
    const int bid = blockIdx.x;
    const int gtid = bid * TPB + tid;

    // ================= Phase A: init + per-box precompute ==================
    for (int t = gtid; t < NBOX * 32; t += NTH) g_supp[t] = 0u;
    if (gtid == 0) { g_cnt_gg = 0; g_cnt_pg = 0; g_cnt_sp = 0; }
    if (gtid < NBOX) {
        g_rowbest[gtid] = 0xFFFFFFFFull;
        float lab = labels[gtid];
        float sgm = 1.0f / (1.0f + expf(-cls[gtid]));
        out[gtid] = (sgm > 0.55f && lab > 0.55f) ? 1.0f : 0.0f;
        out[NBOX + gtid] = lab;
    }
    for (int t = gtid; t < 2 * NBOX; t += NTH) {
        bool isgt = (t < NBOX);
        int i = isgt ? t : t - NBOX;
        const float* p = isgt ? (gt_boxes + i * 8) : (pred_boxes + i * 7);
        Box b;
        b.cx = p[0]; b.cy = p[1];
        float z = p[2], dx = p[3], dy = p[4], dz = p[5], r = p[6];
        b.hx = 0.5f * dx; b.hy = 0.5f * dy;
        float csn = cosf(r), snn = sinf(r);
        b.cs = csn; b.sn = snn;
        const float sxt[4] = {1.f, 1.f, -1.f, -1.f};
        const float syt[4] = {1.f, -1.f, -1.f, 1.f};
#pragma unroll
        for (int q = 0; q < 4; q++) {
            float lx = sxt[q] * b.hx, ly = syt[q] * b.hy;
            b.corx[q] = lx * csn - ly * snn + b.cx;
            b.cory[q] = lx * snn + ly * csn + b.cy;
        }
        b.rad = sqrtf(b.hx * b.hx + b.hy * b.hy) + 5e-4f;
        b.zmin = z - dz * 0.5f;
        b.zmax = z + dz * 0.5f;
        b.area = dx * dy;
        b.vol = dx * dy * dz;
        b.pad = 0.f;
        if (isgt) {
            g_gt[i] = b;
            g_qgt[i] = make_float4(b.cx, b.cy, b.rad, b.zmin);
            g_zmaxgt[i] = b.zmax;
        } else {
            g_pred[i] = b;
            g_qpred[i] = make_float4(b.cx, b.cy, b.rad, b.zmin);
            g_zmaxpred[i] = b.zmax;
        }
    }
    gbar();

    // === Phase B: block0 sorts || others prune -> subbar -> heavy IoU ======
    if (bid == 0) {
        unsigned long long* key = (unsigned long long*)s_mem;
        for (int t = tid; t < NBOX; t += TPB) {
            unsigned u = __float_as_uint(labels[t]);
            u = (u & 0x80000000u) ? ~u : (u | 0x80000000u);
            key[t] = ((unsigned long long)(~u) << 32) | (unsigned)t;
        }
        __syncthreads();
        for (int k2 = 2; k2 <= NBOX; k2 <<= 1) {
            for (int j = k2 >> 1; j > 0; j >>= 1) {
                for (int t = tid; t < NBOX; t += TPB) {
                    int ixj = t ^ j;
                    if (ixj > t) {
                        unsigned long long A = key[t], B = key[ixj];
                        bool up = ((t & k2) == 0);
                        if ((A > B) == up) { key[t] = B; key[ixj] = A; }
                    }
                }
                __syncthreads();
            }
        }
        for (int t = tid; t < NBOX; t += TPB) {
            int orig = (int)(unsigned)(key[t] & 0xFFFFFFFFull);
            g_order[t] = orig;
            g_pos[orig] = t;
        }
    } else {
        // prune gg (upper triangle) and pg
        const int NW = (GRID - 1) * (TPB / 32);
        int gw = (bid - 1) * (TPB / 32) + (tid >> 5);
        int lane = tid & 31;
        for (int row = gw; row < 2 * NBOX; row += NW) {
            if (row < NBOX) {
                float4 qi = g_qgt[row];
                for (int jj = lane; jj < NBOX; jj += 32) {
                    bool pass = false;
                    if (jj > row) {
                        float4 qj = g_qgt[jj];
                        float dx = qi.x - qj.x, dy = qi.y - qj.y;
                        float rr = qi.z + qj.z;
                        pass = (dx * dx + dy * dy <= rr * rr);
                    }
                    emit_pair(pass, ((unsigned)row << 10) | (unsigned)jj,
                              &g_cnt_gg, g_pairs_gg);
                }
            } else {
                int i = row - NBOX;
                float4 qi = g_qpred[i];
                float zmaxi = g_zmaxpred[i];
                for (int jj = lane; jj < NBOX; jj += 32) {
                    float4 qj = g_qgt[jj];
                    float oh = fminf(zmaxi, g_zmaxgt[jj]) - fmaxf(qi.w, qj.w);
                    float dx = qi.x - qj.x, dy = qi.y - qj.y;
                    float rr = qi.z + qj.z;
                    bool pass = (oh > 0.f) && (dx * dx + dy * dy <= rr * rr);
                    emit_pair(pass, ((unsigned)i << 10) | (unsigned)jj,
                              &g_cnt_pg, g_pairs_pg);
                }
            }
        }
        subbar();
        int n_gg = *(volatile int*)&g_cnt_gg; if (n_gg > MAXP) n_gg = MAXP;
        int n_pg = *(volatile int*)&g_cnt_pg; if (n_pg > MAXP) n_pg = MAXP;
        int ntot = n_gg + n_pg;
        const int NT2 = (GRID - 1) * TPB;
        for (int idx = (bid - 1) * TPB + tid; idx < ntot; idx += NT2) {
            if (idx < n_gg) {
                unsigned pr = g_pairs_gg[idx];
                int i = pr >> 10, j = pr & 1023;
                float inter = inter_area(g_gt[i], g_gt[j]);
                float iou = inter / fmaxf(g_gt[i].area + g_gt[j].area - inter, EPSF);
                if (iou > NMS_TH) {
                    int s = atomicAdd(&g_cnt_sp, 1);
                    if (s < MAXSP) g_sp[s] = pr;
                }
            } else {
                int t2 = idx - n_gg;
                unsigned pr = g_pairs_pg[t2];
                int i = pr >> 10, j = pr & 1023;
                const Box& a = g_pred[i];
                const Box& b = g_gt[j];
                float inter = inter_area(a, b);
                float oh = fmaxf(fminf(a.zmax, b.zmax) - fmaxf(a.zmin, b.zmin), 0.f);
                float i3 = inter * oh;
                g_ioupg[t2] = i3 / fmaxf(a.vol + b.vol - i3, EPSF);
            }
        }
    }
    gbar();

    // ===== Phase C (block 0): scatter supp bits -> smem copy -> NMS scan ====
    if (bid == 0) {
        int nsp = *(volatile int*)&g_cnt_sp; if (nsp > MAXSP) nsp = MAXSP;
        for (int t = tid; t < nsp; t += TPB) {
            unsigned pr = g_sp[t];
            int i = pr >> 10, j = pr & 1023;
            int a = g_pos[i], b = g_pos[j];
            int lo = min(a, b), hi = max(a, b);
            atomicOr(&g_supp[lo * 32 + (hi >> 5)], 1u << (hi & 31));
        }
        __threadfence();
        __syncthreads();
        {   // 128KB copy, L2-coherent loads (bypass possibly-stale L1)
            const uint4* src = (const uint4*)g_supp;
            uint4* dst = (uint4*)s_mem;
            for (int t = tid; t < NBOX * 32 / 4; t += TPB) dst[t] = __ldcg(src + t);
        }
        __syncthreads();
        if (tid < 32) {
            unsigned lane = tid;
            unsigned keep = FULLM;          // lane l owns keep-word l
            for (int w = 0; w < 32; w++) {
                unsigned kcur = __shfl_sync(FULLM, keep, w);
                // diagonal block: lane u holds row (w*32+u), word w (bits > u only)
                unsigned mdiaw = s_mem[(w * 32 + lane) * 32 + w];
                unsigned conf = __ballot_sync(FULLM,
                    ((kcur >> lane) & 1u) && (mdiaw & kcur));
                if (conf == 0) {
                    // no alive-alive suppression inside word: all alive kept
                    unsigned bits = kcur;
                    while (bits) {
                        int u = __ffs(bits) - 1; bits &= bits - 1;
                        keep &= ~s_mem[(w * 32 + u) * 32 + lane];
                    }
                } else {
                    unsigned kc = kcur;
                    while (kc) {
                        int u = __ffs(kc) - 1;          // u is kept
                        unsigned mdia_u = __shfl_sync(FULLM, mdiaw, u);
                        keep &= ~s_mem[(w * 32 + u) * 32 + lane];
                        kc = (kc & (kc - 1)) & ~mdia_u; // drop u + its victims
                    }
                }
            }
#pragma unroll
            for (int b = 0; b < 32; b++) {
                int a = (int)lane * 32 + b;
                g_keep_orig[g_order[a]] = (int)((keep >> b) & 1u);
            }
        }
    }
    gbar();

    // ============ Phase E: keep-filtered per-row argmax reduction ==========
    {
        int n = *(volatile int*)&g_cnt_pg; if (n > MAXP) n = MAXP;
        for (int idx = gtid; idx < n; idx += NTH) {
            unsigned pr = g_pairs_pg[idx];
            int i = pr >> 10, j = pr & 1023;
            if (g_keep_orig[j]) {
                unsigned long long pack =
                    ((unsigned long long)__float_as_uint(g_ioupg[idx]) << 32) |
                    (unsigned long long)(0xFFFFFFFFu - (unsigned)j);
                atomicMax(&g_rowbest[i], pack);
            }
        }
    }
    gbar();

    // ======================= Phase F: finalize output ======================
    if (gtid < NBOX) {
        unsigned long long b = *((volatile unsigned long long*)&g_rowbest[gtid]);
        float v = __uint_as_float((unsigned)(b >> 32));
        unsigned idx = 0xFFFFFFFFu - (unsigned)(b & 0xFFFFFFFFull);
        float mo = (v > 0.75f) ? 1.0f : ((v < 0.25f) ? 0.0f : v);
        out[2 * NBOX + gtid] = mo;
        out[3 * NBOX + gtid] = (float)idx;
    }
}

// ---------------------------------------------------------------------------
extern "C" void kernel_launch(void* const* d_in, const int* in_sizes, int n_in,
                              void* d_out, int out_size) {
    const float* labels = (const float*)d_in[0];
    const float* pred   = (const float*)d_in[1];
    const float* gt     = (const float*)d_in[2];
    const float* cls    = (const float*)d_in[3];
    for (int i = 0; i < n_in; i++) {
        if (in_sizes[i] == NBOX * 7) pred = (const float*)d_in[i];
        else if (in_sizes[i] == NBOX * 8) gt = (const float*)d_in[i];
    }
    float* out = (float*)d_out;

    cudaFuncSetAttribute(mega_kernel,
                         cudaFuncAttributeMaxDynamicSharedMemorySize, 131072);
    mega_kernel<<<GRID, TPB, 131072>>>(labels, pred, gt, cls, out);
}

// round 8
// speedup vs baseline: 1.0023x; 1.0023x over previous
#include <cuda_runtime.h>
#include <math.h>

#define NBOX 1024
#define EPSF 1e-8f
#define NMS_TH 0.1f
#define MAXP (1<<18)
#define MAXSP (1<<16)
#define GRID 148
#define TPB 512
#define NTH (GRID*TPB)
#define NWARP (GRID*(TPB/32))
#define FULLM 0xFFFFFFFFu

struct Box {
    float cx, cy, hx, hy, cs, sn;
    float corx[4], cory[4];
    float rad, zmin, zmax, area, vol;
    float pad;
};

__device__ Box g_gt[NBOX];
__device__ Box g_pred[NBOX];
__device__ float4 g_qgt[NBOX];     // cx, cy, rad, zmin
__device__ float4 g_qpred[NBOX];
__device__ float g_zmaxgt[NBOX];
__device__ float g_zmaxpred[NBOX];
__device__ unsigned g_key[NBOX];         // order-preserving mapped score bits
__device__ unsigned g_supp[NBOX * 32];   // sorted-space suppression bits (upper-tri)
__device__ int g_order[NBOX];
__device__ int g_pos[NBOX];
__device__ int g_keep_orig[NBOX];
__device__ int g_cnt_gg;
__device__ int g_cnt_pg;
__device__ int g_cnt_sp;
__device__ unsigned g_pairs_gg[MAXP];
__device__ unsigned g_pairs_pg[MAXP];
__device__ unsigned g_sp[MAXSP];         // orig-space suppression pairs
__device__ float g_ioupg[MAXP];
__device__ unsigned long long g_rowbest[NBOX];

// monotonic grid barrier (replay-safe), raw spin
__device__ unsigned g_bar_arrive;
__device__ volatile unsigned g_bar_release;

__device__ __forceinline__ void gbar() {
    __syncthreads();
    if (threadIdx.x == 0) {
        __threadfence();
        unsigned t = atomicAdd(&g_bar_arrive, 1u) + 1u;
        unsigned need = ((t + GRID - 1u) / GRID) * GRID;
        if (t == need) g_bar_release = need;
        else while (g_bar_release < need) { }
        __threadfence();
    }
    __syncthreads();
}

// ---------------------------------------------------------------------------
// Rotated-rect intersection — bit-identical to the passing R1 math.
// ---------------------------------------------------------------------------
__device__ float inter_area(const Box& a, const Box& b) {
    float px[24], py[24];
    int k = 0;

#pragma unroll
    for (int q = 0; q < 4; q++) {
        float dxp = a.corx[q] - b.cx, dyp = a.cory[q] - b.cy;
        float lx =  dxp * b.cs + dyp * b.sn;
        float ly = -dxp * b.sn + dyp * b.cs;
        if (fabsf(lx) <= b.hx + 1e-5f && fabsf(ly) <= b.hy + 1e-5f) {
            px[k] = a.corx[q]; py[k] = a.cory[q]; k++;
        }
    }
#pragma unroll
    for (int q = 0; q < 4; q++) {
        float dxp = b.corx[q] - a.cx, dyp = b.cory[q] - a.cy;
        float lx =  dxp * a.cs + dyp * a.sn;
        float ly = -dxp * a.sn + dyp * a.cs;
        if (fabsf(lx) <= a.hx + 1e-5f && fabsf(ly) <= a.hy + 1e-5f) {
            px[k] = b.corx[q]; py[k] = b.cory[q]; k++;
        }
    }
#pragma unroll
    for (int p = 0; p < 4; p++) {
        float a0x = a.corx[p], a0y = a.cory[p];
        float a1x = a.corx[(p + 1) & 3], a1y = a.cory[(p + 1) & 3];
        float d1x = a1x - a0x, d1y = a1y - a0y;
#pragma unroll
        for (int q = 0; q < 4; q++) {
            float b0x = b.corx[q], b0y = b.cory[q];
            float b1x = b.corx[(q + 1) & 3], b1y = b.cory[(q + 1) & 3];
            float d2x = b1x - b0x, d2y = b1y - b0y;
            float r0x = b0x - a0x, r0y = b0y - a0y;
            float den = d1x * d2y - d1y * d2x;
            if (fabsf(den) > EPSF) {
                float t = (r0x * d2y - r0y * d2x) / den;
                float u = (r0x * d1y - r0y * d1x) / den;
                if (t >= 0.f && t <= 1.f && u >= 0.f && u <= 1.f) {
                    px[k] = a0x + t * d1x;
                    py[k] = a0y + t * d1y;
                    k++;
                }
            }
        }
    }

    if (k < 3) return 0.f;

    float sx = 0.f, sy = 0.f;
    for (int i = 0; i < k; i++) { sx += px[i]; sy += py[i]; }
    float fk = (float)k;
    float cxm = sx / fk, cym = sy / fk;

    float ang[24];
    for (int i = 0; i < k; i++) {
        px[i] -= cxm; py[i] -= cym;
        ang[i] = atan2f(py[i], px[i]);
    }
    for (int i = 1; i < k; i++) {
        float ax = px[i], ay = py[i], aa = ang[i];
        int j = i - 1;
        while (j >= 0 && ang[j] > aa) {
            px[j + 1] = px[j]; py[j + 1] = py[j]; ang[j + 1] = ang[j];
            j--;
        }
        px[j + 1] = ax; py[j + 1] = ay; ang[j + 1] = aa;
    }
    float s = 0.f;
    for (int i = 0; i < k; i++) {
        int j = (i + 1 == k) ? 0 : (i + 1);
        s += px[i] * py[j] - py[i] * px[j];
    }
    return 0.5f * fabsf(s);
}

__device__ __forceinline__ void emit_pair(bool pass, unsigned code,
                                          int* cnt, unsigned* arr) {
    unsigned m = __ballot_sync(FULLM, pass);
    if (!m) return;
    int lane = threadIdx.x & 31;
    int leader = __ffs(m) - 1;
    int base = 0;
    if (lane == leader) base = atomicAdd(cnt, __popc(m));
    base = __shfl_sync(FULLM, base, leader);
    if (pass) {
        int idx = base + __popc(m & ((1u << lane) - 1u));
        if (idx < MAXP) arr[idx] = code;
    }
}

// ---------------------------------------------------------------------------
__global__ __launch_bounds__(TPB, 1)
void mega_kernel(const float* __restrict__ labels,
                 const float* __restrict__ pred_boxes,
                 const float* __restrict__ gt_boxes,
                 const float* __restrict__ cls,
                 float* __restrict__ out) {
    extern __shared__ unsigned s_mem[];   // 128KB: supp copy for the scan
    const int tid = threadIdx.x;
    const int bid = blockIdx.x;
    const int gtid = bid * TPB + tid;
    const int lane = tid & 31;
    const int gw = (gtid >> 5);           // global warp id

    // ================= Phase A: init + per-box precompute ==================
    for (int t = gtid; t < NBOX * 32; t += NTH) g_supp[t] = 0u;
    if (gtid == 0) { g_cnt_gg = 0; g_cnt_pg = 0; g_cnt_sp = 0; }
    if (gtid < NBOX) {
        g_rowbest[gtid] = 0xFFFFFFFFull;
        float lab = labels[gtid];
        unsigned u = __float_as_uint(lab);
        g_key[gtid] = (u & 0x80000000u) ? ~u : (u | 0x80000000u);
        float sgm = 1.0f / (1.0f + expf(-cls[gtid]));
        out[gtid] = (sgm > 0.55f && lab > 0.55f) ? 1.0f : 0.0f;
        out[NBOX + gtid] = lab;
    }
    for (int t = gtid; t < 2 * NBOX; t += NTH) {
        bool isgt = (t < NBOX);
        int i = isgt ? t : t - NBOX;
        const float* p = isgt ? (gt_boxes + i * 8) : (pred_boxes + i * 7);
        Box b;
        b.cx = p[0]; b.cy = p[1];
        float z = p[2], dx = p[3], dy = p[4], dz = p[5], r = p[6];
        b.hx = 0.5f * dx; b.hy = 0.5f * dy;
        float csn = cosf(r), snn = sinf(r);
        b.cs = csn; b.sn = snn;
        const float sxt[4] = {1.f, 1.f, -1.f, -1.f};
        const float syt[4] = {1.f, -1.f, -1.f, 1.f};
#pragma unroll
        for (int q = 0; q < 4; q++) {
            float lx = sxt[q] * b.hx, ly = syt[q] * b.hy;
            b.corx[q] = lx * csn - ly * snn + b.cx;
            b.cory[q] = lx * snn + ly * csn + b.cy;
        }
        b.rad = sqrtf(b.hx * b.hx + b.hy * b.hy) + 5e-4f;
        b.zmin = z - dz * 0.5f;
        b.zmax = z + dz * 0.5f;
        b.area = dx * dy;
        b.vol = dx * dy * dz;
        b.pad = 0.f;
        if (isgt) {
            g_gt[i] = b;
            g_qgt[i] = make_float4(b.cx, b.cy, b.rad, b.zmin);
            g_zmaxgt[i] = b.zmax;
        } else {
            g_pred[i] = b;
            g_qpred[i] = make_float4(b.cx, b.cy, b.rad, b.zmin);
            g_zmaxpred[i] = b.zmax;
        }
    }
    gbar();

    // ==== Phase B: distributed rank-sort + prune gg + prune pg (3072 rows) ==
    for (int row = gw; row < 3 * NBOX; row += NWARP) {
        if (row < NBOX) {
            // rank of key[row] in descending stable order
            unsigned ki = g_key[row];
            int cnt = 0;
            for (int j = lane; j < NBOX; j += 32) {
                unsigned kj = g_key[j];
                cnt += (kj > ki) || (kj == ki && j < row);
            }
#pragma unroll
            for (int o = 16; o > 0; o >>= 1)
                cnt += __shfl_down_sync(FULLM, cnt, o);
            if (lane == 0) {
                g_pos[row] = cnt;
                g_order[cnt] = row;
            }
        } else if (row < 2 * NBOX) {
            int i = row - NBOX;              // gt x gt upper triangle
            float4 qi = g_qgt[i];
            for (int jj = lane; jj < NBOX; jj += 32) {
                bool pass = false;
                if (jj > i) {
                    float4 qj = g_qgt[jj];
                    float dx = qi.x - qj.x, dy = qi.y - qj.y;
                    float rr = qi.z + qj.z;
                    pass = (dx * dx + dy * dy <= rr * rr);
                }
                emit_pair(pass, ((unsigned)i << 10) | (unsigned)jj,
                          &g_cnt_gg, g_pairs_gg);
            }
        } else {
            int i = row - 2 * NBOX;          // pred x gt
            float4 qi = g_qpred[i];
            float zmaxi = g_zmaxpred[i];
            for (int jj = lane; jj < NBOX; jj += 32) {
                float4 qj = g_qgt[jj];
                float oh = fminf(zmaxi, g_zmaxgt[jj]) - fmaxf(qi.w, qj.w);
                float dx = qi.x - qj.x, dy = qi.y - qj.y;
                float rr = qi.z + qj.z;
                bool pass = (oh > 0.f) && (dx * dx + dy * dy <= rr * rr);
                emit_pair(pass, ((unsigned)i << 10) | (unsigned)jj,
                          &g_cnt_pg, g_pairs_pg);
            }
        }
    }
    gbar();

    // ================= Phase C: heavy IoU over all pairs ===================
    {
        int n_gg = *(volatile int*)&g_cnt_gg; if (n_gg > MAXP) n_gg = MAXP;
        int n_pg = *(volatile int*)&g_cnt_pg; if (n_pg > MAXP) n_pg = MAXP;
        int ntot = n_gg + n_pg;
        for (int idx = gtid; idx < ntot; idx += NTH) {
            if (idx < n_gg) {
                unsigned pr = g_pairs_gg[idx];
                int i = pr >> 10, j = pr & 1023;
                float inter = inter_area(g_gt[i], g_gt[j]);
                float iou = inter / fmaxf(g_gt[i].area + g_gt[j].area - inter, EPSF);
                if (iou > NMS_TH) {
                    int s = atomicAdd(&g_cnt_sp, 1);
                    if (s < MAXSP) g_sp[s] = pr;
                }
            } else {
                int t2 = idx - n_gg;
                unsigned pr = g_pairs_pg[t2];
                int i = pr >> 10, j = pr & 1023;
                const Box& a = g_pred[i];
                const Box& b = g_gt[j];
                float inter = inter_area(a, b);
                float oh = fmaxf(fminf(a.zmax, b.zmax) - fmaxf(a.zmin, b.zmin), 0.f);
                float i3 = inter * oh;
                g_ioupg[t2] = i3 / fmaxf(a.vol + b.vol - i3, EPSF);
            }
        }
    }
    gbar();

    // ============ Phase D: scatter supp pairs into sorted bitmask ==========
    {
        int nsp = *(volatile int*)&g_cnt_sp; if (nsp > MAXSP) nsp = MAXSP;
        for (int t = gtid; t < nsp; t += NTH) {
            unsigned pr = g_sp[t];
            int i = pr >> 10, j = pr & 1023;
            int a = g_pos[i], b = g_pos[j];
            int lo = min(a, b), hi = max(a, b);
            atomicOr(&g_supp[lo * 32 + (hi >> 5)], 1u << (hi & 31));
        }
    }
    gbar();

    // ================ Phase E (block 0): smem copy + NMS scan ==============
    if (bid == 0) {
        {   // 128KB copy, L2-coherent loads
            const uint4* src = (const uint4*)g_supp;
            uint4* dst = (uint4*)s_mem;
            for (int t = tid; t < NBOX * 32 / 4; t += TPB) dst[t] = __ldcg(src + t);
        }
        __syncthreads();
        if (tid < 32) {
            unsigned keep = FULLM;          // lane l owns keep-word l
            for (int w = 0; w < 32; w++) {
                unsigned kcur = __shfl_sync(FULLM, keep, w);
                unsigned mdiaw = s_mem[(w * 32 + lane) * 32 + w];
                unsigned conf = __ballot_sync(FULLM,
                    ((kcur >> lane) & 1u) && (mdiaw & kcur));
                if (conf == 0) {
                    unsigned bits = kcur;
                    while (bits) {
                        int u = __ffs(bits) - 1; bits &= bits - 1;
                        keep &= ~s_mem[(w * 32 + u) * 32 + lane];
                    }
                } else {
                    unsigned kc = kcur;
                    while (kc) {
                        int u = __ffs(kc) - 1;
                        unsigned mdia_u = __shfl_sync(FULLM, mdiaw, u);
                        keep &= ~s_mem[(w * 32 + u) * 32 + lane];
                        kc = (kc & (kc - 1)) & ~mdia_u;
                    }
                }
            }
#pragma unroll
            for (int b = 0; b < 32; b++) {
                int a = lane * 32 + b;
                g_keep_orig[g_order[a]] = (int)((keep >> b) & 1u);
            }
        }
    }
    gbar();

    // ============ Phase F: keep-filtered per-row argmax reduction ==========
    {
        int n = *(volatile int*)&g_cnt_pg; if (n > MAXP) n = MAXP;
        for (int idx = gtid; idx < n; idx += NTH) {
            unsigned pr = g_pairs_pg[idx];
            int i = pr >> 10, j = pr & 1023;
            if (g_keep_orig[j]) {
                unsigned long long pack =
                    ((unsigned long long)__float_as_uint(g_ioupg[idx]) << 32) |
                    (unsigned long long)(0xFFFFFFFFu - (unsigned)j);
                atomicMax(&g_rowbest[i], pack);
            }
        }
    }
    gbar();

    // ======================= Phase G: finalize output ======================
    if (gtid < NBOX) {
        unsigned long long b = *((volatile unsigned long long*)&g_rowbest[gtid]);
        float v = __uint_as_float((unsigned)(b >> 32));
        unsigned idx = 0xFFFFFFFFu - (unsigned)(b & 0xFFFFFFFFull);
        float mo = (v > 0.75f) ? 1.0f : ((v < 0.25f) ? 0.0f : v);
        out[2 * NBOX + gtid] = mo;
        out[3 * NBOX + gtid] = (float)idx;
    }
}

// ---------------------------------------------------------------------------
extern "C" void kernel_launch(void* const* d_in, const int* in_sizes, int n_in,
                              void* d_out, int out_size) {
    const float* labels = (const float*)d_in[0];
    const float* pred   = (const float*)d_in[1];
    const float* gt     = (const float*)d_in[2];
    const float* cls    = (const float*)d_in[3];
    for (int i = 0; i < n_in; i++) {
        if (in_sizes[i] == NBOX * 7) pred = (const float*)d_in[i];
        else if (in_sizes[i] == NBOX * 8) gt = (const float*)d_in[i];
    }
    float* out = (float*)d_out;

    cudaFuncSetAttribute(mega_kernel,
                         cudaFuncAttributeMaxDynamicSharedMemorySize, 131072);
    mega_kernel<<<GRID, TPB, 131072>>>(labels, pred, gt, cls, out);
}